// round 9
// baseline (speedup 1.0000x reference)
#include <cuda_runtime.h>
#include <cuda_bf16.h>
#include <cstdint>
#include <cstddef>

#define B_ 64
#define T_ 512
#define I_ 128
#define H_ 512
#define O_ 128
#define C_ 10
#define SCAN_NC 64

typedef unsigned long long ull;

// ---------------- scratch ----------------
__device__ float g_Wcomb[H_ * I_];
__device__ float g_bcomb[H_];
__device__ float g_xs[(size_t)T_ * B_ * H_];   // [t][b][h]
__device__ float g_z [(size_t)T_ * B_ * H_];   // [t][b][h]
__device__ float g_hT[2 * H_ * B_];            // ping-pong, [buf][k][b]
__device__ unsigned g_arrive[SCAN_NC * 32];    // per-CTA flag, 128B apart

// ---------------- helpers ----------------
__device__ __forceinline__ void ffma2(ull& d, ull a, ull b) {
    asm("fma.rn.f32x2 %0, %1, %2, %0;" : "+l"(d) : "l"(a), "l"(b));
}
__device__ __forceinline__ ull pack2(float x, float y) {
    ull r; asm("mov.b64 %0, {%1, %2};" : "=l"(r) : "f"(x), "f"(y)); return r;
}
__device__ __forceinline__ void unpack2(ull v, float& x, float& y) {
    asm("mov.b64 {%0, %1}, %2;" : "=f"(x), "=f"(y) : "l"(v));
}
__device__ __forceinline__ unsigned ldcg_u32(const unsigned* p) {
    unsigned v; asm volatile("ld.global.cg.u32 %0, [%1];" : "=r"(v) : "l"(p)); return v;
}

__global__ void reset_kernel() { g_arrive[threadIdx.x * 32] = 0u; }

// ---------------- prep: W_comb = W_ih @ W_init ; b_comb = W_ih@b_init + b_ih ----
__global__ void __launch_bounds__(128) prep_kernel(
    const float* __restrict__ Wih, const float* __restrict__ bih,
    const float* __restrict__ Winit, const float* __restrict__ binit)
{
    __shared__ float wrow[H_];
    __shared__ float part[128];
    const int g = blockIdx.x;
    const int tid = threadIdx.x;
    for (int k = tid; k < H_; k += 128) wrow[k] = Wih[g * H_ + k];
    __syncthreads();

    float acc = 0.f;
    #pragma unroll 8
    for (int k = 0; k < H_; k++) acc += wrow[k] * Winit[k * I_ + tid];
    g_Wcomb[g * I_ + tid] = acc;

    float p = 0.f;
    for (int k = tid; k < H_; k += 128) p += wrow[k] * binit[k];
    part[tid] = p; __syncthreads();
    for (int s = 64; s > 0; s >>= 1) {
        if (tid < s) part[tid] += part[tid + s];
        __syncthreads();
    }
    if (tid == 0) g_bcomb[g] = part[0] + bih[g];
}

// ---------------- xs = batch @ W_comb^T + b_comb -> g_xs[t][b][g] ----------------
__global__ void __launch_bounds__(256) xs_kernel(const float* __restrict__ batch)
{
    __shared__ __align__(16) float Asm[32][68];
    __shared__ __align__(16) float Bsm[32][68];
    const int tid = threadIdx.x;
    const int g0 = blockIdx.x * 64;
    const int r0 = blockIdx.y * 64;
    const int tx = tid & 15, ty = tid >> 4;
    const int lm = tid & 63, lq = tid >> 6;

    float acc[4][4] = {};

    for (int kc = 0; kc < I_; kc += 32) {
        __syncthreads();
        {
            const float* src = batch + (size_t)(r0 + lm) * I_ + kc + lq * 8;
            float4 v0 = *(const float4*)(src + 0);
            float4 v1 = *(const float4*)(src + 4);
            const int kb = lq * 8;
            Asm[kb+0][lm]=v0.x; Asm[kb+1][lm]=v0.y; Asm[kb+2][lm]=v0.z; Asm[kb+3][lm]=v0.w;
            Asm[kb+4][lm]=v1.x; Asm[kb+5][lm]=v1.y; Asm[kb+6][lm]=v1.z; Asm[kb+7][lm]=v1.w;
        }
        {
            const float* src = g_Wcomb + (size_t)(g0 + lm) * I_ + kc + lq * 8;
            float4 v0 = *(const float4*)(src + 0);
            float4 v1 = *(const float4*)(src + 4);
            const int kb = lq * 8;
            Bsm[kb+0][lm]=v0.x; Bsm[kb+1][lm]=v0.y; Bsm[kb+2][lm]=v0.z; Bsm[kb+3][lm]=v0.w;
            Bsm[kb+4][lm]=v1.x; Bsm[kb+5][lm]=v1.y; Bsm[kb+6][lm]=v1.z; Bsm[kb+7][lm]=v1.w;
        }
        __syncthreads();
        #pragma unroll 8
        for (int k = 0; k < 32; k++) {
            float4 a = *(const float4*)&Asm[k][ty * 4];
            float4 b = *(const float4*)&Bsm[k][tx * 4];
            acc[0][0]+=a.x*b.x; acc[0][1]+=a.x*b.y; acc[0][2]+=a.x*b.z; acc[0][3]+=a.x*b.w;
            acc[1][0]+=a.y*b.x; acc[1][1]+=a.y*b.y; acc[1][2]+=a.y*b.z; acc[1][3]+=a.y*b.w;
            acc[2][0]+=a.z*b.x; acc[2][1]+=a.z*b.y; acc[2][2]+=a.z*b.z; acc[2][3]+=a.z*b.w;
            acc[3][0]+=a.w*b.x; acc[3][1]+=a.w*b.y; acc[3][2]+=a.w*b.z; acc[3][3]+=a.w*b.w;
        }
    }
    float4 bc = *(const float4*)&g_bcomb[g0 + tx * 4];
    #pragma unroll
    for (int i = 0; i < 4; i++) {
        int r = r0 + ty * 4 + i;
        int b = r / T_, t = r % T_;
        float4 v;
        v.x = acc[i][0] + bc.x; v.y = acc[i][1] + bc.y;
        v.z = acc[i][2] + bc.z; v.w = acc[i][3] + bc.w;
        *(float4*)&g_xs[((size_t)t * B_ + b) * H_ + g0 + tx * 4] = v;
    }
}

// ---------------- persistent scan: 64 CTAs, 8 h-cols per CTA ----------------
// EXACT Round-4 verified body; sole change: kk-loop pragma unroll 4 -> 8.
// smem: whh packed [512][8] ull (32KB) + part [8 warps][512 floats swizzled] (16KB)
__global__ void __launch_bounds__(256) scan_kernel(
    const float* __restrict__ Whh, const float* __restrict__ bhh)
{
    extern __shared__ char smem[];
    ull*   whh_p = (ull*)smem;                 // [512][8]
    float* part  = (float*)(smem + 32768);     // [8][512], swizzled

    const int tid = threadIdx.x;
    const int w = tid >> 5, l = tid & 31;
    const int cta = blockIdx.x;
    const int g0 = cta * 8;

    for (int i = tid; i < H_ * 8; i += 256) {
        int k = i >> 3, g = i & 7;
        float v = Whh[(size_t)(g0 + g) * H_ + k];
        whh_p[i] = pack2(v, v);
    }
    const int idx1 = tid, idx2 = tid + 256;
    const int b1 = idx1 >> 3, gg1 = idx1 & 7;
    const int b2 = idx2 >> 3, gg2 = idx2 & 7;
    const float bh1 = bhh[g0 + gg1];
    const float bh2 = bhh[g0 + gg2];
    // swizzled slot address: slot s (owner lane lo=s>>4, j=s&15) at 16*lo+((j+(lo>>1))&15)
    const int lo1 = idx1 >> 4, j1 = idx1 & 15;
    const int lo2 = idx2 >> 4, j2 = idx2 & 15;
    const int rd1 = (lo1 << 4) + ((j1 + (lo1 >> 1)) & 15);
    const int rd2 = (lo2 << 4) + ((j2 + (lo2 >> 1)) & 15);
    __syncthreads();

    const int ks = w * 64;
    const int pbase = w * 512 + l * 16;
    const int rot = (l >> 1) & 15;

    for (int t = 0; t < T_; t++) {
        const int wb = t & 1, rb = wb ^ 1;

        // prefetch xs for this step (independent of h; hides under spin)
        float xt1 = __ldg(&g_xs[((size_t)t * B_ + b1) * H_ + g0 + gg1]);
        float xt2 = __ldg(&g_xs[((size_t)t * B_ + b2) * H_ + g0 + gg2]);

        if (t > 0) {
            // wait for all CTAs to have finished step t-1
            if (tid < SCAN_NC) {
                const unsigned* fp = &g_arrive[tid * 32];
                while (ldcg_u32(fp) < (unsigned)t) {}
                __threadfence();   // acquire: order h-reads after flag-observe
            }
            __syncthreads();

            ull acc[8];
            #pragma unroll
            for (int g = 0; g < 8; g++) acc[g] = 0ull;
            const float* hsrc = g_hT + rb * (H_ * B_);
            #pragma unroll 8
            for (int kk = 0; kk < 64; kk++) {
                const int k = ks + kk;
                float2 h2 = __ldcg((const float2*)(hsrc + k * B_ + 2 * l));
                ull hh = pack2(h2.x, h2.y);
                const ulonglong2* wp = (const ulonglong2*)&whh_p[k * 8];
                ulonglong2 w01 = wp[0], w23 = wp[1], w45 = wp[2], w67 = wp[3];
                ffma2(acc[0], w01.x, hh); ffma2(acc[1], w01.y, hh);
                ffma2(acc[2], w23.x, hh); ffma2(acc[3], w23.y, hh);
                ffma2(acc[4], w45.x, hh); ffma2(acc[5], w45.y, hh);
                ffma2(acc[6], w67.x, hh); ffma2(acc[7], w67.y, hh);
            }
            // lane l owns slots 16l+g (b=2l) and 16l+8+g (b=2l+1), swizzled
            #pragma unroll
            for (int g = 0; g < 8; g++) {
                float x, y; unpack2(acc[g], x, y);
                part[pbase + ((g + rot) & 15)]     = x;
                part[pbase + ((g + 8 + rot) & 15)] = y;
            }
        }
        __syncthreads();

        {
            float val = bh1 + xt1;
            if (t > 0) {
                float s = 0.f;
                #pragma unroll
                for (int ww = 0; ww < 8; ww++) s += part[ww * 512 + rd1];
                val += s;
            }
            float h = tanhf(val);
            g_z[((size_t)t * B_ + b1) * H_ + g0 + gg1] = h;
            __stcg(&g_hT[wb * (H_ * B_) + (g0 + gg1) * B_ + b1], h);
        }
        {
            float val = bh2 + xt2;
            if (t > 0) {
                float s = 0.f;
                #pragma unroll
                for (int ww = 0; ww < 8; ww++) s += part[ww * 512 + rd2];
                val += s;
            }
            float h = tanhf(val);
            g_z[((size_t)t * B_ + b2) * H_ + g0 + gg2] = h;
            __stcg(&g_hT[wb * (H_ * B_) + (g0 + gg2) * B_ + b2], h);
        }

        __threadfence();
        __syncthreads();
        if (tid == 0) __stcg(&g_arrive[cta * 32], (unsigned)(t + 1));
    }
}

// ---------------- predicted = z @ W_dec^T + b_dec -> out[b][t][o] ----------------
__global__ void __launch_bounds__(256) dec_kernel(
    const float* __restrict__ Wdec, const float* __restrict__ bdec,
    float* __restrict__ out)
{
    __shared__ __align__(16) float Asm[32][68];
    __shared__ __align__(16) float Bsm[32][68];
    const int tid = threadIdx.x;
    const int o0 = blockIdx.x * 64;
    const int r0 = blockIdx.y * 64;
    const int tx = tid & 15, ty = tid >> 4;
    const int lm = tid & 63, lq = tid >> 6;

    float acc[4][4] = {};

    for (int kc = 0; kc < H_; kc += 32) {
        __syncthreads();
        {
            const float* src = g_z + (size_t)(r0 + lm) * H_ + kc + lq * 8;
            float4 v0 = *(const float4*)(src + 0);
            float4 v1 = *(const float4*)(src + 4);
            const int kb = lq * 8;
            Asm[kb+0][lm]=v0.x; Asm[kb+1][lm]=v0.y; Asm[kb+2][lm]=v0.z; Asm[kb+3][lm]=v0.w;
            Asm[kb+4][lm]=v1.x; Asm[kb+5][lm]=v1.y; Asm[kb+6][lm]=v1.z; Asm[kb+7][lm]=v1.w;
        }
        {
            const float* src = Wdec + (size_t)(o0 + lm) * H_ + kc + lq * 8;
            float4 v0 = *(const float4*)(src + 0);
            float4 v1 = *(const float4*)(src + 4);
            const int kb = lq * 8;
            Bsm[kb+0][lm]=v0.x; Bsm[kb+1][lm]=v0.y; Bsm[kb+2][lm]=v0.z; Bsm[kb+3][lm]=v0.w;
            Bsm[kb+4][lm]=v1.x; Bsm[kb+5][lm]=v1.y; Bsm[kb+6][lm]=v1.z; Bsm[kb+7][lm]=v1.w;
        }
        __syncthreads();
        #pragma unroll 8
        for (int k = 0; k < 32; k++) {
            float4 a = *(const float4*)&Asm[k][ty * 4];
            float4 b = *(const float4*)&Bsm[k][tx * 4];
            acc[0][0]+=a.x*b.x; acc[0][1]+=a.x*b.y; acc[0][2]+=a.x*b.z; acc[0][3]+=a.x*b.w;
            acc[1][0]+=a.y*b.x; acc[1][1]+=a.y*b.y; acc[1][2]+=a.y*b.z; acc[1][3]+=a.y*b.w;
            acc[2][0]+=a.z*b.x; acc[2][1]+=a.z*b.y; acc[2][2]+=a.z*b.z; acc[2][3]+=a.z*b.w;
            acc[3][0]+=a.w*b.x; acc[3][1]+=a.w*b.y; acc[3][2]+=a.w*b.z; acc[3][3]+=a.w*b.w;
        }
    }
    float4 bc = *(const float4*)&bdec[o0 + tx * 4];
    #pragma unroll
    for (int i = 0; i < 4; i++) {
        int r = r0 + ty * 4 + i;
        int t = r / B_, b = r % B_;
        float4 v;
        v.x = acc[i][0] + bc.x; v.y = acc[i][1] + bc.y;
        v.z = acc[i][2] + bc.z; v.w = acc[i][3] + bc.w;
        *(float4*)&out[((size_t)b * T_ + t) * O_ + o0 + tx * 4] = v;
    }
}

// ---------------- logits = z[b, last_idx] @ W_cls^T + b_cls ----------------
__global__ void __launch_bounds__(256) cls_kernel(
    const float* __restrict__ mask, const float* __restrict__ Wcls,
    const float* __restrict__ bcls, float* __restrict__ out_logits)
{
    __shared__ float sm[256];
    const int b = blockIdx.x;
    const int tid = threadIdx.x;
    const int w = tid >> 5, l = tid & 31;

    float p = mask[(size_t)b * T_ + tid] + mask[(size_t)b * T_ + tid + 256];
    sm[tid] = p; __syncthreads();
    for (int s = 128; s > 0; s >>= 1) {
        if (tid < s) sm[tid] += sm[tid + s];
        __syncthreads();
    }
    const int last = (int)(sm[0] + 0.5f) - 1;
    const float* zf = g_z + ((size_t)last * B_ + b) * H_;

    for (int c = w; c < C_; c += 8) {
        float s = 0.f;
        for (int k = l; k < H_; k += 32) s += zf[k] * Wcls[(size_t)c * H_ + k];
        #pragma unroll
        for (int off = 16; off; off >>= 1) s += __shfl_down_sync(0xffffffffu, s, off);
        if (l == 0) out_logits[(size_t)b * C_ + c] = s + bcls[c];
    }
}

// ---------------- launch ----------------
extern "C" void kernel_launch(void* const* d_in, const int* in_sizes, int n_in,
                              void* d_out, int out_size)
{
    const float* batch = (const float*)d_in[0];
    const float* mask  = (const float*)d_in[1];
    const float* Winit = (const float*)d_in[2];
    const float* binit = (const float*)d_in[3];
    const float* Wih   = (const float*)d_in[4];
    const float* bih   = (const float*)d_in[5];
    const float* Whh   = (const float*)d_in[6];
    const float* bhh   = (const float*)d_in[7];
    const float* Wdec  = (const float*)d_in[8];
    const float* bdec  = (const float*)d_in[9];
    const float* Wcls  = (const float*)d_in[10];
    const float* bcls  = (const float*)d_in[11];

    float* out_pred   = (float*)d_out;
    float* out_logits = (float*)d_out + (size_t)B_ * T_ * O_;

    reset_kernel<<<1, SCAN_NC>>>();
    prep_kernel<<<H_, 128>>>(Wih, bih, Winit, binit);
    xs_kernel<<<dim3(H_ / 64, (B_ * T_) / 64), 256>>>(batch);
    scan_kernel<<<SCAN_NC, 256, 49152>>>(Whh, bhh);
    dec_kernel<<<dim3(O_ / 64, (B_ * T_) / 64), 256>>>(Wdec, bdec, out_pred);
    cls_kernel<<<B_, 256>>>(mask, Wcls, bcls, out_logits);
}

// round 14
// speedup vs baseline: 2.1372x; 2.1372x over previous
#include <cuda_runtime.h>
#include <cuda_bf16.h>
#include <cstdint>
#include <cstddef>

#define B_ 64
#define T_ 512
#define I_ 128
#define H_ 512
#define O_ 128
#define C_ 10
#define SCAN_NC 64

// ---------------- scratch ----------------
__device__ float g_Wcomb[H_ * I_];
__device__ float g_bcomb[H_];
__device__ float g_xs[(size_t)T_ * B_ * H_];   // [t][b][h]
__device__ float g_z [(size_t)T_ * B_ * H_];   // [t][b][h]
__device__ float g_hT[2 * H_ * B_];            // ping-pong, [buf][k][b]
__device__ unsigned g_arrive[SCAN_NC * 32];    // per-CTA flag, 128B apart

__device__ __forceinline__ unsigned ldcg_u32(const unsigned* p) {
    unsigned v; asm volatile("ld.global.cg.u32 %0, [%1];" : "=r"(v) : "l"(p)); return v;
}

__global__ void reset_kernel() { g_arrive[threadIdx.x * 32] = 0u; }

// ---------------- prep: W_comb = W_ih @ W_init ; b_comb = W_ih@b_init + b_ih ----
__global__ void __launch_bounds__(128) prep_kernel(
    const float* __restrict__ Wih, const float* __restrict__ bih,
    const float* __restrict__ Winit, const float* __restrict__ binit)
{
    __shared__ float wrow[H_];
    __shared__ float part[128];
    const int g = blockIdx.x;
    const int tid = threadIdx.x;
    for (int k = tid; k < H_; k += 128) wrow[k] = Wih[g * H_ + k];
    __syncthreads();

    float acc = 0.f;
    #pragma unroll 8
    for (int k = 0; k < H_; k++) acc += wrow[k] * Winit[k * I_ + tid];
    g_Wcomb[g * I_ + tid] = acc;

    float p = 0.f;
    for (int k = tid; k < H_; k += 128) p += wrow[k] * binit[k];
    part[tid] = p; __syncthreads();
    for (int s = 64; s > 0; s >>= 1) {
        if (tid < s) part[tid] += part[tid + s];
        __syncthreads();
    }
    if (tid == 0) g_bcomb[g] = part[0] + bih[g];
}

// ---------------- xs = batch @ W_comb^T + b_comb -> g_xs[t][b][g] ----------------
__global__ void __launch_bounds__(256) xs_kernel(const float* __restrict__ batch)
{
    __shared__ __align__(16) float Asm[32][68];
    __shared__ __align__(16) float Bsm[32][68];
    const int tid = threadIdx.x;
    const int g0 = blockIdx.x * 64;
    const int r0 = blockIdx.y * 64;
    const int tx = tid & 15, ty = tid >> 4;
    const int lm = tid & 63, lq = tid >> 6;

    float acc[4][4] = {};

    for (int kc = 0; kc < I_; kc += 32) {
        __syncthreads();
        {
            const float* src = batch + (size_t)(r0 + lm) * I_ + kc + lq * 8;
            float4 v0 = *(const float4*)(src + 0);
            float4 v1 = *(const float4*)(src + 4);
            const int kb = lq * 8;
            Asm[kb+0][lm]=v0.x; Asm[kb+1][lm]=v0.y; Asm[kb+2][lm]=v0.z; Asm[kb+3][lm]=v0.w;
            Asm[kb+4][lm]=v1.x; Asm[kb+5][lm]=v1.y; Asm[kb+6][lm]=v1.z; Asm[kb+7][lm]=v1.w;
        }
        {
            const float* src = g_Wcomb + (size_t)(g0 + lm) * I_ + kc + lq * 8;
            float4 v0 = *(const float4*)(src + 0);
            float4 v1 = *(const float4*)(src + 4);
            const int kb = lq * 8;
            Bsm[kb+0][lm]=v0.x; Bsm[kb+1][lm]=v0.y; Bsm[kb+2][lm]=v0.z; Bsm[kb+3][lm]=v0.w;
            Bsm[kb+4][lm]=v1.x; Bsm[kb+5][lm]=v1.y; Bsm[kb+6][lm]=v1.z; Bsm[kb+7][lm]=v1.w;
        }
        __syncthreads();
        #pragma unroll 8
        for (int k = 0; k < 32; k++) {
            float4 a = *(const float4*)&Asm[k][ty * 4];
            float4 b = *(const float4*)&Bsm[k][tx * 4];
            acc[0][0]+=a.x*b.x; acc[0][1]+=a.x*b.y; acc[0][2]+=a.x*b.z; acc[0][3]+=a.x*b.w;
            acc[1][0]+=a.y*b.x; acc[1][1]+=a.y*b.y; acc[1][2]+=a.y*b.z; acc[1][3]+=a.y*b.w;
            acc[2][0]+=a.z*b.x; acc[2][1]+=a.z*b.y; acc[2][2]+=a.z*b.z; acc[2][3]+=a.z*b.w;
            acc[3][0]+=a.w*b.x; acc[3][1]+=a.w*b.y; acc[3][2]+=a.w*b.z; acc[3][3]+=a.w*b.w;
        }
    }
    float4 bc = *(const float4*)&g_bcomb[g0 + tx * 4];
    #pragma unroll
    for (int i = 0; i < 4; i++) {
        int r = r0 + ty * 4 + i;
        int b = r / T_, t = r % T_;
        float4 v;
        v.x = acc[i][0] + bc.x; v.y = acc[i][1] + bc.y;
        v.z = acc[i][2] + bc.z; v.w = acc[i][3] + bc.w;
        *(float4*)&g_xs[((size_t)t * B_ + b) * H_ + g0 + tx * 4] = v;
    }
}

// ---------------- persistent scan: 64 CTAs, 8 h-cols per CTA ----------------
// R9-verified structure; sole change: inline-asm packed math -> plain scalar C
// (bitwise-identical FFMA results, but ptxas can now pipeline the LDGs).
// smem: wsm [512][8] f32 (16KB) + part [8 warps][512 swizzled] (16KB) = 32KB
__global__ void __launch_bounds__(256) scan_kernel(
    const float* __restrict__ Whh, const float* __restrict__ bhh)
{
    extern __shared__ char smem[];
    float* wsm  = (float*)smem;                // [k][g] 16KB
    float* part = (float*)(smem + 16384);      // [8][512], swizzled

    const int tid = threadIdx.x;
    const int w = tid >> 5, l = tid & 31;
    const int cta = blockIdx.x;
    const int g0 = cta * 8;

    for (int i = tid; i < H_ * 8; i += 256) {
        int k = i >> 3, g = i & 7;
        wsm[i] = Whh[(size_t)(g0 + g) * H_ + k];   // wsm[k*8+g]
    }
    const int idx1 = tid, idx2 = tid + 256;
    const int b1 = idx1 >> 3, gg1 = idx1 & 7;
    const int b2 = idx2 >> 3, gg2 = idx2 & 7;
    const float bh1 = bhh[g0 + gg1];
    const float bh2 = bhh[g0 + gg2];
    // swizzled slot address: slot s (owner lane lo=s>>4, j=s&15) at 16*lo+((j+(lo>>1))&15)
    const int lo1 = idx1 >> 4, j1 = idx1 & 15;
    const int lo2 = idx2 >> 4, j2 = idx2 & 15;
    const int rd1 = (lo1 << 4) + ((j1 + (lo1 >> 1)) & 15);
    const int rd2 = (lo2 << 4) + ((j2 + (lo2 >> 1)) & 15);
    __syncthreads();

    const int ks = w * 64;
    const int pbase = w * 512 + l * 16;
    const int rot = (l >> 1) & 15;

    for (int t = 0; t < T_; t++) {
        const int wb = t & 1, rb = wb ^ 1;

        // prefetch xs for this step (independent of h; hides under spin)
        float xt1 = __ldg(&g_xs[((size_t)t * B_ + b1) * H_ + g0 + gg1]);
        float xt2 = __ldg(&g_xs[((size_t)t * B_ + b2) * H_ + g0 + gg2]);

        if (t > 0) {
            // wait for all CTAs to have finished step t-1
            if (tid < SCAN_NC) {
                const unsigned* fp = &g_arrive[tid * 32];
                while (ldcg_u32(fp) < (unsigned)t) {}
                __threadfence();   // acquire: order h-reads after flag-observe
            }
            __syncthreads();

            float acc0[8], acc1[8];   // acc0: b=2l, acc1: b=2l+1
            #pragma unroll
            for (int g = 0; g < 8; g++) { acc0[g] = 0.f; acc1[g] = 0.f; }

            const float* hsrc = g_hT + rb * (H_ * B_) + ks * B_ + 2 * l;
            #pragma unroll 8
            for (int kk = 0; kk < 64; kk++) {
                float2 h2 = __ldcg((const float2*)(hsrc + kk * B_));
                const float4 wa = *(const float4*)&wsm[(ks + kk) * 8];
                const float4 wc = *(const float4*)&wsm[(ks + kk) * 8 + 4];
                acc0[0] += wa.x * h2.x;  acc1[0] += wa.x * h2.y;
                acc0[1] += wa.y * h2.x;  acc1[1] += wa.y * h2.y;
                acc0[2] += wa.z * h2.x;  acc1[2] += wa.z * h2.y;
                acc0[3] += wa.w * h2.x;  acc1[3] += wa.w * h2.y;
                acc0[4] += wc.x * h2.x;  acc1[4] += wc.x * h2.y;
                acc0[5] += wc.y * h2.x;  acc1[5] += wc.y * h2.y;
                acc0[6] += wc.z * h2.x;  acc1[6] += wc.z * h2.y;
                acc0[7] += wc.w * h2.x;  acc1[7] += wc.w * h2.y;
            }
            // lane l owns slots 16l+g (b=2l) and 16l+8+g (b=2l+1), swizzled
            #pragma unroll
            for (int g = 0; g < 8; g++) {
                part[pbase + ((g + rot) & 15)]     = acc0[g];
                part[pbase + ((g + 8 + rot) & 15)] = acc1[g];
            }
        }
        __syncthreads();

        {
            float val = bh1 + xt1;
            if (t > 0) {
                float s = 0.f;
                #pragma unroll
                for (int ww = 0; ww < 8; ww++) s += part[ww * 512 + rd1];
                val += s;
            }
            float h = tanhf(val);
            g_z[((size_t)t * B_ + b1) * H_ + g0 + gg1] = h;
            __stcg(&g_hT[wb * (H_ * B_) + (g0 + gg1) * B_ + b1], h);
        }
        {
            float val = bh2 + xt2;
            if (t > 0) {
                float s = 0.f;
                #pragma unroll
                for (int ww = 0; ww < 8; ww++) s += part[ww * 512 + rd2];
                val += s;
            }
            float h = tanhf(val);
            g_z[((size_t)t * B_ + b2) * H_ + g0 + gg2] = h;
            __stcg(&g_hT[wb * (H_ * B_) + (g0 + gg2) * B_ + b2], h);
        }

        __threadfence();
        __syncthreads();
        if (tid == 0) __stcg(&g_arrive[cta * 32], (unsigned)(t + 1));
    }
}

// ---------------- predicted = z @ W_dec^T + b_dec -> out[b][t][o] ----------------
__global__ void __launch_bounds__(256) dec_kernel(
    const float* __restrict__ Wdec, const float* __restrict__ bdec,
    float* __restrict__ out)
{
    __shared__ __align__(16) float Asm[32][68];
    __shared__ __align__(16) float Bsm[32][68];
    const int tid = threadIdx.x;
    const int o0 = blockIdx.x * 64;
    const int r0 = blockIdx.y * 64;
    const int tx = tid & 15, ty = tid >> 4;
    const int lm = tid & 63, lq = tid >> 6;

    float acc[4][4] = {};

    for (int kc = 0; kc < H_; kc += 32) {
        __syncthreads();
        {
            const float* src = g_z + (size_t)(r0 + lm) * H_ + kc + lq * 8;
            float4 v0 = *(const float4*)(src + 0);
            float4 v1 = *(const float4*)(src + 4);
            const int kb = lq * 8;
            Asm[kb+0][lm]=v0.x; Asm[kb+1][lm]=v0.y; Asm[kb+2][lm]=v0.z; Asm[kb+3][lm]=v0.w;
            Asm[kb+4][lm]=v1.x; Asm[kb+5][lm]=v1.y; Asm[kb+6][lm]=v1.z; Asm[kb+7][lm]=v1.w;
        }
        {
            const float* src = Wdec + (size_t)(o0 + lm) * H_ + kc + lq * 8;
            float4 v0 = *(const float4*)(src + 0);
            float4 v1 = *(const float4*)(src + 4);
            const int kb = lq * 8;
            Bsm[kb+0][lm]=v0.x; Bsm[kb+1][lm]=v0.y; Bsm[kb+2][lm]=v0.z; Bsm[kb+3][lm]=v0.w;
            Bsm[kb+4][lm]=v1.x; Bsm[kb+5][lm]=v1.y; Bsm[kb+6][lm]=v1.z; Bsm[kb+7][lm]=v1.w;
        }
        __syncthreads();
        #pragma unroll 8
        for (int k = 0; k < 32; k++) {
            float4 a = *(const float4*)&Asm[k][ty * 4];
            float4 b = *(const float4*)&Bsm[k][tx * 4];
            acc[0][0]+=a.x*b.x; acc[0][1]+=a.x*b.y; acc[0][2]+=a.x*b.z; acc[0][3]+=a.x*b.w;
            acc[1][0]+=a.y*b.x; acc[1][1]+=a.y*b.y; acc[1][2]+=a.y*b.z; acc[1][3]+=a.y*b.w;
            acc[2][0]+=a.z*b.x; acc[2][1]+=a.z*b.y; acc[2][2]+=a.z*b.z; acc[2][3]+=a.z*b.w;
            acc[3][0]+=a.w*b.x; acc[3][1]+=a.w*b.y; acc[3][2]+=a.w*b.z; acc[3][3]+=a.w*b.w;
        }
    }
    float4 bc = *(const float4*)&bdec[o0 + tx * 4];
    #pragma unroll
    for (int i = 0; i < 4; i++) {
        int r = r0 + ty * 4 + i;
        int t = r / B_, b = r % B_;
        float4 v;
        v.x = acc[i][0] + bc.x; v.y = acc[i][1] + bc.y;
        v.z = acc[i][2] + bc.z; v.w = acc[i][3] + bc.w;
        *(float4*)&out[((size_t)b * T_ + t) * O_ + o0 + tx * 4] = v;
    }
}

// ---------------- logits = z[b, last_idx] @ W_cls^T + b_cls ----------------
__global__ void __launch_bounds__(256) cls_kernel(
    const float* __restrict__ mask, const float* __restrict__ Wcls,
    const float* __restrict__ bcls, float* __restrict__ out_logits)
{
    __shared__ float sm[256];
    const int b = blockIdx.x;
    const int tid = threadIdx.x;
    const int w = tid >> 5, l = tid & 31;

    float p = mask[(size_t)b * T_ + tid] + mask[(size_t)b * T_ + tid + 256];
    sm[tid] = p; __syncthreads();
    for (int s = 128; s > 0; s >>= 1) {
        if (tid < s) sm[tid] += sm[tid + s];
        __syncthreads();
    }
    const int last = (int)(sm[0] + 0.5f) - 1;
    const float* zf = g_z + ((size_t)last * B_ + b) * H_;

    for (int c = w; c < C_; c += 8) {
        float s = 0.f;
        for (int k = l; k < H_; k += 32) s += zf[k] * Wcls[(size_t)c * H_ + k];
        #pragma unroll
        for (int off = 16; off; off >>= 1) s += __shfl_down_sync(0xffffffffu, s, off);
        if (l == 0) out_logits[(size_t)b * C_ + c] = s + bcls[c];
    }
}

// ---------------- launch ----------------
extern "C" void kernel_launch(void* const* d_in, const int* in_sizes, int n_in,
                              void* d_out, int out_size)
{
    const float* batch = (const float*)d_in[0];
    const float* mask  = (const float*)d_in[1];
    const float* Winit = (const float*)d_in[2];
    const float* binit = (const float*)d_in[3];
    const float* Wih   = (const float*)d_in[4];
    const float* bih   = (const float*)d_in[5];
    const float* Whh   = (const float*)d_in[6];
    const float* bhh   = (const float*)d_in[7];
    const float* Wdec  = (const float*)d_in[8];
    const float* bdec  = (const float*)d_in[9];
    const float* Wcls  = (const float*)d_in[10];
    const float* bcls  = (const float*)d_in[11];

    float* out_pred   = (float*)d_out;
    float* out_logits = (float*)d_out + (size_t)B_ * T_ * O_;

    reset_kernel<<<1, SCAN_NC>>>();
    prep_kernel<<<H_, 128>>>(Wih, bih, Winit, binit);
    xs_kernel<<<dim3(H_ / 64, (B_ * T_) / 64), 256>>>(batch);
    scan_kernel<<<SCAN_NC, 256, 32768>>>(Whh, bhh);
    dec_kernel<<<dim3(O_ / 64, (B_ * T_) / 64), 256>>>(Wdec, bdec, out_pred);
    cls_kernel<<<B_, 256>>>(mask, Wcls, bcls, out_logits);
}